// round 17
// baseline (speedup 1.0000x reference)
#include <cuda_runtime.h>
#include <cuda_bf16.h>
#include <math.h>

#define NNODES 50000
#define HDIM   128
#define NHEADS 8
#define HEADD  16
#define NRELS  100
#define NEDGES 800000
#define FFDIM  512

typedef __nv_bfloat16  bf16;
typedef __nv_bfloat162 bf162;

// ---------------- scratch (device globals; no allocation allowed) ----------
// Zero-initialized at module load; normalize_kernel re-zeroes g_agg/g_denom
// after consuming them, so the zero-state invariant holds for every call.
__device__ float g_xa[NNODES * HDIM];       // LN1 output fp32 (residual for W2)
__device__ float g_denom[NNODES * NHEADS];
__device__ float g_agg[NNODES * HDIM];      // fp32 atomic accumulation buffer
__device__ float g_qc[HDIM];
__device__ float g_kc[HDIM];

// bf16 operands (single precision bf16 everywhere)
__device__ bf16 g_qb[NNODES * HDIM];
__device__ bf16 g_kb[NNODES * HDIM];
__device__ bf16 g_vb[NNODES * HDIM];
__device__ bf16 g_relb[NRELS * HDIM];
__device__ bf16 g_node_h[NNODES * HDIM];
__device__ bf16 g_agg_h[NNODES * HDIM];
__device__ bf16 g_xa_h[NNODES * HDIM];
__device__ bf16 g_hid_h[NNODES * FFDIM];
__device__ bf16 g_wq_h[HDIM * HDIM];
__device__ bf16 g_wk_h[HDIM * HDIM];
__device__ bf16 g_wv_h[HDIM * HDIM];
__device__ bf16 g_wo_h[HDIM * HDIM];
__device__ bf16 g_w1_h[FFDIM * HDIM];
__device__ bf16 g_w2_h[HDIM * FFDIM];

// ---------------- helpers --------------------------------------------------
__device__ __forceinline__ void cvt4_store_hi(float4 v, bf16* dh) {
    bf162 a = __floats2bfloat162_rn(v.x, v.y);
    bf162 b = __floats2bfloat162_rn(v.z, v.w);
    *(uint2*)dh = make_uint2(*(unsigned*)&a, *(unsigned*)&b);
}

// ---------------- fused prep: qc fold + node/rel cvt + weight cvt ---------
#define NN4 (NNODES * HDIM / 4)     // 1,600,000 float4 units
#define NW4 49152                   // total weight float4 units

__global__ void prep_kernel(const float* __restrict__ node, const float* __restrict__ rel,
                            const float* __restrict__ qemb,
                            const float* __restrict__ Wq, const float* __restrict__ bq,
                            const float* __restrict__ Wk, const float* __restrict__ bk,
                            const float* __restrict__ Wv, const float* __restrict__ Wo,
                            const float* __restrict__ W1, const float* __restrict__ W2) {
    int gid = blockIdx.x * blockDim.x + threadIdx.x;
    if (gid < NN4) {
        float4 v = *(const float4*)(node + (size_t)gid * 4);
        cvt4_store_hi(v, g_node_h + (size_t)gid * 4);
    }
    if (gid < NRELS * HDIM / 4) {
        float4 v = *(const float4*)(rel + (size_t)gid * 4);
        cvt4_store_hi(v, g_relb + (size_t)gid * 4);
    }
    if (gid < NW4) {
        const float* src; bf16* dh; int cols, ld; int i = gid;
        if (i < 4096)       { src = Wq; dh = g_wq_h; cols = HDIM;  ld = 2 * HDIM; }
        else if (i < 8192)  { src = Wk; dh = g_wk_h; cols = HDIM;  ld = 2 * HDIM; i -= 4096; }
        else if (i < 12288) { src = Wv; dh = g_wv_h; cols = HDIM;  ld = HDIM;     i -= 8192; }
        else if (i < 16384) { src = Wo; dh = g_wo_h; cols = HDIM;  ld = HDIM;     i -= 12288; }
        else if (i < 32768) { src = W1; dh = g_w1_h; cols = HDIM;  ld = HDIM;     i -= 16384; }
        else                { src = W2; dh = g_w2_h; cols = FFDIM; ld = FFDIM;    i -= 32768; }
        int c4 = cols / 4;
        int r = i / c4, c = (i - r * c4) * 4;
        float4 v = *(const float4*)(src + (size_t)r * ld + c);
        cvt4_store_hi(v, dh + (size_t)r * cols + c);
    }
    if (gid < 2 * HDIM) {   // qc/kc fold (block 0 only)
        int t = gid;
        if (t < HDIM) {
            float s = bq[t];
            const float* w = Wq + (size_t)t * (2 * HDIM) + HDIM;
            #pragma unroll 8
            for (int j = 0; j < HDIM; j++) s += qemb[j] * w[j];
            g_qc[t] = s;
        } else {
            int o = t - HDIM;
            float s = bk[o];
            const float* w = Wk + (size_t)o * (2 * HDIM) + HDIM;
            #pragma unroll 8
            for (int j = 0; j < HDIM; j++) s += qemb[j] * w[j];
            g_kc[o] = s;
        }
    }
}

// =====================================================================
// single-term bf16 tensor-core GEMM: C[M,Nout] = A[M,K] @ W[Nout,K]^T
// 3-stage cp.async pipeline.
// MODE 1: +bias,GELU -> bf16       MODE 3: +bias -> bf16
// MODE 4: +bias+resid+LN -> fp32   MODE 5: +bias+resid+LN -> fp32 + bf16
// =====================================================================
#define LDB 40                              // bf16 elems per smem row (80B pad)
#define TILE_E (128 * LDB)                  // elems per tile
#define TILE_B (TILE_E * 2)                 // bytes per tile
#define BUF_E  (2 * TILE_E)                 // A + B
#define NSTAGE 3
#define GEMM_SMEM_BYTES (NSTAGE * BUF_E * 2)    // 61440 bytes

__device__ __forceinline__ void cpa(unsigned d, const void* s, int sz) {
    asm volatile("cp.async.cg.shared.global [%0], [%1], 16, %2;"
                 :: "r"(d), "l"(s), "r"(sz));
}

__device__ __forceinline__ void mma16(float* c, const unsigned* a,
                                      unsigned b0, unsigned b1) {
    asm("mma.sync.aligned.m16n8k16.row.col.f32.bf16.bf16.f32 "
        "{%0,%1,%2,%3}, {%4,%5,%6,%7}, {%8,%9}, {%0,%1,%2,%3};"
        : "+f"(c[0]), "+f"(c[1]), "+f"(c[2]), "+f"(c[3])
        : "r"(a[0]), "r"(a[1]), "r"(a[2]), "r"(a[3]), "r"(b0), "r"(b1));
}

__device__ __forceinline__ void issue_chunk(
    const bf16* __restrict__ Ah, const bf16* __restrict__ Bh,
    int M, int K, int m0, int n0, int k0, bf16* sbuf, int t)
{
    int r = t >> 1;
    int okA = (m0 + r < M);
    size_t aoff = (size_t)(okA ? m0 + r : 0) * K + k0;
    size_t boff = (size_t)(n0 + r) * K + k0;
    int szA = okA ? 16 : 0;
    unsigned base = (unsigned)__cvta_generic_to_shared(sbuf) + r * (LDB * 2);
    #pragma unroll
    for (int u = 0; u < 2; u++) {
        int o = (t & 1) * 8 + u * 16;              // element offset within 32
        unsigned d = base + o * 2;
        cpa(d,          Ah + aoff + o, szA);
        cpa(d + TILE_B, Bh + boff + o, 16);
    }
}

template <int MODE>
__device__ __forceinline__ void gemm_bf_body(
    const bf16* __restrict__ Ah, const bf16* __restrict__ Bh,
    const float* __restrict__ bias, const float* __restrict__ resid,
    float* __restrict__ C, bf16* __restrict__ Ch,
    const float* __restrict__ lng, const float* __restrict__ lnb,
    int M, int K, int Nout, int n0)
{
    extern __shared__ bf16 smem[];
    int t = threadIdx.x;
    int m0 = blockIdx.x * 128;
    int lane = t & 31, warp = t >> 5;
    int wm = warp & 3, wn = warp >> 2;
    int gid = lane >> 2, tig = lane & 3;

    float acc[2][8][4];
    #pragma unroll
    for (int mt = 0; mt < 2; mt++)
        #pragma unroll
        for (int nt = 0; nt < 8; nt++)
            #pragma unroll
            for (int j = 0; j < 4; j++) acc[mt][nt][j] = 0.0f;

    int nch = K >> 5;
    issue_chunk(Ah, Bh, M, K, m0, n0, 0, smem, t);
    asm volatile("cp.async.commit_group;");
    if (nch > 1) {
        issue_chunk(Ah, Bh, M, K, m0, n0, 32, smem + BUF_E, t);
        asm volatile("cp.async.commit_group;");
    }

    for (int ch = 0; ch < nch; ch++) {
        if (ch + 2 < nch) {
            issue_chunk(Ah, Bh, M, K, m0, n0, (ch + 2) << 5,
                        smem + ((ch + 2) % NSTAGE) * BUF_E, t);
            asm volatile("cp.async.commit_group;");
        }
        int last = (nch - 1 < ch + 2) ? nch - 1 : ch + 2;
        int remain = last - ch;   // groups still in flight beyond chunk ch
        if (remain >= 2)      asm volatile("cp.async.wait_group 2;");
        else if (remain == 1) asm volatile("cp.async.wait_group 1;");
        else                  asm volatile("cp.async.wait_group 0;");
        __syncthreads();
        const bf16* sAh = smem + (ch % NSTAGE) * BUF_E;
        const bf16* sBh = sAh + TILE_E;
        #pragma unroll
        for (int s = 0; s < 2; s++) {
            int kb = s * 16 + 2 * tig;
            unsigned ah[2][4];
            #pragma unroll
            for (int mt = 0; mt < 2; mt++) {
                int rb = (wm * 32 + mt * 16 + gid) * LDB + kb;
                ah[mt][0] = *(const unsigned*)(sAh + rb);
                ah[mt][1] = *(const unsigned*)(sAh + rb + 8 * LDB);
                ah[mt][2] = *(const unsigned*)(sAh + rb + 8);
                ah[mt][3] = *(const unsigned*)(sAh + rb + 8 * LDB + 8);
            }
            #pragma unroll
            for (int nt = 0; nt < 8; nt++) {
                int rn = (wn * 64 + nt * 8 + gid) * LDB + kb;
                unsigned bh0 = *(const unsigned*)(sBh + rn);
                unsigned bh1 = *(const unsigned*)(sBh + rn + 8);
                #pragma unroll
                for (int mt = 0; mt < 2; mt++)
                    mma16(acc[mt][nt], ah[mt], bh0, bh1);
            }
        }
        __syncthreads();
    }

    // ---- epilogue ----
    if (MODE == 1 || MODE == 3) {
        #pragma unroll
        for (int mt = 0; mt < 2; mt++) {
            #pragma unroll
            for (int nt = 0; nt < 8; nt++) {
                int col = n0 + wn * 64 + nt * 8 + 2 * tig;
                float bv0 = bias[col], bv1 = bias[col + 1];
                #pragma unroll
                for (int h = 0; h < 2; h++) {
                    int r = m0 + wm * 32 + mt * 16 + gid + 8 * h;
                    if (r >= M) continue;
                    float o0 = acc[mt][nt][2 * h]     + bv0;
                    float o1 = acc[mt][nt][2 * h + 1] + bv1;
                    if (MODE == 1) {
                        o0 = 0.5f * o0 * (1.0f + erff(o0 * 0.70710678118654752f));
                        o1 = 0.5f * o1 * (1.0f + erff(o1 * 0.70710678118654752f));
                    }
                    bf162 hh = __floats2bfloat162_rn(o0, o1);
                    *(unsigned*)(Ch + (size_t)r * Nout + col) = *(unsigned*)&hh;
                }
            }
        }
    } else {
        // MODE 4/5: bias + resid + LayerNorm (Nout == 128, full row per CTA)
        #pragma unroll
        for (int mt = 0; mt < 2; mt++)
            #pragma unroll
            for (int nt = 0; nt < 8; nt++) {
                int col = n0 + wn * 64 + nt * 8 + 2 * tig;
                float bv0 = bias[col], bv1 = bias[col + 1];
                #pragma unroll
                for (int h = 0; h < 2; h++) {
                    int r = m0 + wm * 32 + mt * 16 + gid + 8 * h;
                    float2 rv = (r < M) ? *(const float2*)(resid + (size_t)r * Nout + col)
                                        : make_float2(0.f, 0.f);
                    acc[mt][nt][2 * h]     += bv0 + rv.x;
                    acc[mt][nt][2 * h + 1] += bv1 + rv.y;
                }
            }
        float* red = (float*)smem;     // [2][128][2] floats = 2 KB
        #pragma unroll
        for (int mt = 0; mt < 2; mt++)
            #pragma unroll
            for (int h = 0; h < 2; h++) {
                float s = 0.f, q = 0.f;
                #pragma unroll
                for (int nt = 0; nt < 8; nt++) {
                    float a0 = acc[mt][nt][2 * h], a1 = acc[mt][nt][2 * h + 1];
                    s += a0 + a1; q += a0 * a0 + a1 * a1;
                }
                s += __shfl_xor_sync(0xffffffffu, s, 1);
                q += __shfl_xor_sync(0xffffffffu, q, 1);
                s += __shfl_xor_sync(0xffffffffu, s, 2);
                q += __shfl_xor_sync(0xffffffffu, q, 2);
                if (tig == 0) {
                    int lr = wm * 32 + mt * 16 + gid + 8 * h;
                    red[(wn * 128 + lr) * 2]     = s;
                    red[(wn * 128 + lr) * 2 + 1] = q;
                }
            }
        __syncthreads();
        #pragma unroll
        for (int mt = 0; mt < 2; mt++)
            #pragma unroll
            for (int h = 0; h < 2; h++) {
                int lr = wm * 32 + mt * 16 + gid + 8 * h;
                float s = red[lr * 2]     + red[(128 + lr) * 2];
                float q = red[lr * 2 + 1] + red[(128 + lr) * 2 + 1];
                float mu   = s * (1.0f / 128.0f);
                float var  = q * (1.0f / 128.0f) - mu * mu;
                float rstd = rsqrtf(var + 1e-5f);
                int r = m0 + lr;
                if (r >= M) continue;
                #pragma unroll
                for (int nt = 0; nt < 8; nt++) {
                    int col = n0 + wn * 64 + nt * 8 + 2 * tig;
                    float o0 = (acc[mt][nt][2 * h]     - mu) * rstd * lng[col]     + lnb[col];
                    float o1 = (acc[mt][nt][2 * h + 1] - mu) * rstd * lng[col + 1] + lnb[col + 1];
                    *(float2*)(C + (size_t)r * Nout + col) = make_float2(o0, o1);
                    if (MODE == 5) {
                        bf162 hh = __floats2bfloat162_rn(o0, o1);
                        *(unsigned*)(Ch + (size_t)r * Nout + col) = *(unsigned*)&hh;
                    }
                }
            }
    }
}

template <int MODE>
__global__ __launch_bounds__(256, 2)
void gemm_bf_t(const bf16* __restrict__ Ah, const bf16* __restrict__ Bh,
               const float* __restrict__ bias, const float* __restrict__ resid,
               float* __restrict__ C, bf16* __restrict__ Ch,
               const float* __restrict__ lng, const float* __restrict__ lnb,
               int M, int K, int Nout) {
    gemm_bf_body<MODE>(Ah, Bh, bias, resid, C, Ch, lng, lnb,
                       M, K, Nout, blockIdx.y * 128);
}

// QKV: single-term bf16, outputs bf16 straight into edge operands
__global__ __launch_bounds__(256, 2)
void gemm_qkv_bf(const float* __restrict__ bv, int M) {
    int z = blockIdx.z;
    const bf16* Bh = (z == 0) ? g_wq_h : (z == 1) ? g_wk_h : g_wv_h;
    const float* b = (z == 0) ? g_qc : (z == 1) ? g_kc : bv;
    bf16* Ch = (z == 0) ? g_qb : (z == 1) ? g_kb : g_vb;
    gemm_bf_body<3>(g_node_h, Bh, b, nullptr, nullptr, Ch,
                    nullptr, nullptr, M, HDIM, HDIM, 0);
}

// ---------------- fused edge pass (bf16 operands, fp32 math/atomics) ------
__global__ __launch_bounds__(256, 8)
void edge_fused_kernel(const int* __restrict__ ei, const int* __restrict__ et) {
    int w = (blockIdx.x * blockDim.x + threadIdx.x) >> 5;   // edge id
    int lane = threadIdx.x & 31;
    if (w >= NEDGES) return;
    int src = __ldg(ei + w), dst = __ldg(ei + NEDGES + w), r = __ldg(et + w);
    uint2 qu = *(const uint2*)(g_qb  + (size_t)dst * HDIM + lane * 4);
    uint2 ku = *(const uint2*)(g_kb  + (size_t)src * HDIM + lane * 4);
    uint2 cu = *(const uint2*)(g_relb + (size_t)r  * HDIM + lane * 4);
    uint2 vu = *(const uint2*)(g_vb  + (size_t)src * HDIM + lane * 4);
    float2 q0 = __bfloat1622float2(*(bf162*)&qu.x), q1 = __bfloat1622float2(*(bf162*)&qu.y);
    float2 k0 = __bfloat1622float2(*(bf162*)&ku.x), k1 = __bfloat1622float2(*(bf162*)&ku.y);
    float2 c0 = __bfloat1622float2(*(bf162*)&cu.x), c1 = __bfloat1622float2(*(bf162*)&cu.y);
    float2 v0 = __bfloat1622float2(*(bf162*)&vu.x), v1 = __bfloat1622float2(*(bf162*)&vu.y);
    float s = q0.x * (k0.x + c0.x) + q0.y * (k0.y + c0.y)
            + q1.x * (k1.x + c1.x) + q1.y * (k1.y + c1.y);
    s += __shfl_xor_sync(0xffffffffu, s, 1);
    s += __shfl_xor_sync(0xffffffffu, s, 2);
    float es = __expf(s * 0.25f);   // 1/sqrt(16)
    if ((lane & 3) == 0)
        atomicAdd(&g_denom[(size_t)dst * NHEADS + (lane >> 2)], es);
    float* p = g_agg + (size_t)dst * HDIM + lane * 4;
    asm volatile("red.global.add.v4.f32 [%0], {%1,%2,%3,%4};"
                 :: "l"(p), "f"(es * v0.x), "f"(es * v0.y),
                    "f"(es * v1.x), "f"(es * v1.y) : "memory");
}

// ------- normalize -> bf16, then re-zero accumulators for next replay -----
__global__ void normalize_kernel() {
    int i = blockIdx.x * blockDim.x + threadIdx.x;  // over N*NHEADS
    if (i >= NNODES * NHEADS) return;
    float r = 1.0f / (g_denom[i] + 1e-8f);
    float4* p = (float4*)(g_agg + (size_t)i * HEADD);
    #pragma unroll
    for (int u = 0; u < 4; u++) {
        float4 v = p[u];
        v.x *= r; v.y *= r; v.z *= r; v.w *= r;
        cvt4_store_hi(v, g_agg_h + (size_t)i * HEADD + u * 4);
        p[u] = make_float4(0.f, 0.f, 0.f, 0.f);   // self-clean for next call
    }
    g_denom[i] = 0.0f;
}

// ---- fused relational branch: t = rel@relW + relb; out = LN(rel + t@Wc^T) --
__global__ void rel_fused_kernel(const float* __restrict__ rel, const float* __restrict__ relW,
                                 const float* __restrict__ relb, const float* __restrict__ Wc,
                                 const float* __restrict__ bc, const float* __restrict__ gg,
                                 const float* __restrict__ bbn, float* __restrict__ out) {
    __shared__ float er[HDIM];
    __shared__ float tt[FFDIM];
    __shared__ float rs[HDIM], rq[HDIM];
    int r = blockIdx.x, t = threadIdx.x;  // 128 threads
    er[t] = rel[(size_t)r * HDIM + t];
    __syncthreads();
    const float4* e4 = (const float4*)er;
    #pragma unroll
    for (int u = 0; u < 4; u++) {
        int ko = t + u * HDIM;
        const float4* w = (const float4*)(relW + (size_t)ko * HDIM);
        float s = relb[ko];
        #pragma unroll 8
        for (int j = 0; j < HDIM / 4; j++) {
            float4 a = e4[j], b = w[j];
            s += a.x * b.x + a.y * b.y + a.z * b.z + a.w * b.w;
        }
        tt[ko] = s;
    }
    __syncthreads();
    const float4* w = (const float4*)(Wc + (size_t)t * FFDIM);
    const float4* s4 = (const float4*)tt;
    float s = bc[t];
    #pragma unroll 8
    for (int j = 0; j < FFDIM / 4; j++) {
        float4 a = s4[j], b = w[j];
        s += a.x * b.x + a.y * b.y + a.z * b.z + a.w * b.w;
    }
    float pre = er[t] + s;
    rs[t] = pre; rq[t] = pre * pre;
    __syncthreads();
    for (int o = 64; o; o >>= 1) {
        if (t < o) { rs[t] += rs[t + o]; rq[t] += rq[t + o]; }
        __syncthreads();
    }
    float mu   = rs[0] * (1.0f / HDIM);
    float var  = rq[0] * (1.0f / HDIM) - mu * mu;
    float rstd = rsqrtf(var + 1e-5f);
    out[(size_t)r * HDIM + t] = (pre - mu) * rstd * gg[t] + bbn[t];
}

// ---------------- launch ---------------------------------------------------
extern "C" void kernel_launch(void* const* d_in, const int* in_sizes, int n_in,
                              void* d_out, int out_size) {
    const float* node = (const float*)d_in[0];
    const float* qemb = (const float*)d_in[1];
    const int*   ei   = (const int*)d_in[2];
    const int*   et   = (const int*)d_in[3];
    const float* rel  = (const float*)d_in[4];
    const float* Wq   = (const float*)d_in[5];
    const float* bq   = (const float*)d_in[6];
    const float* Wk   = (const float*)d_in[7];
    const float* bk   = (const float*)d_in[8];
    const float* Wv   = (const float*)d_in[9];
    const float* bv   = (const float*)d_in[10];
    const float* Wo   = (const float*)d_in[11];
    const float* bo   = (const float*)d_in[12];
    const float* n1g  = (const float*)d_in[13];
    const float* n1b  = (const float*)d_in[14];
    const float* n2g  = (const float*)d_in[15];
    const float* n2b  = (const float*)d_in[16];
    const float* W1   = (const float*)d_in[17];
    const float* b1   = (const float*)d_in[18];
    const float* W2   = (const float*)d_in[19];
    const float* b2   = (const float*)d_in[20];
    const float* relW = (const float*)d_in[21];
    const float* relb = (const float*)d_in[22];
    const float* Wc   = (const float*)d_in[23];
    const float* bc   = (const float*)d_in[24];
    const float* rng  = (const float*)d_in[25];
    const float* rnb  = (const float*)d_in[26];
    float* out = (float*)d_out;

    float *p_xa;
    bf16 *p_ah, *p_xh, *p_hh, *p_woh, *p_w1h, *p_w2h;
    cudaGetSymbolAddress((void**)&p_xa, g_xa);
    cudaGetSymbolAddress((void**)&p_ah, g_agg_h);
    cudaGetSymbolAddress((void**)&p_xh, g_xa_h);
    cudaGetSymbolAddress((void**)&p_hh, g_hid_h);
    cudaGetSymbolAddress((void**)&p_woh, g_wo_h);
    cudaGetSymbolAddress((void**)&p_w1h, g_w1_h);
    cudaGetSymbolAddress((void**)&p_w2h, g_w2_h);

    // REQUIRED: dynamic smem > 48 KB needs the max-dynamic-smem attribute.
    cudaFuncSetAttribute(gemm_bf_t<1>, cudaFuncAttributeMaxDynamicSharedMemorySize,
                         GEMM_SMEM_BYTES);
    cudaFuncSetAttribute(gemm_bf_t<4>, cudaFuncAttributeMaxDynamicSharedMemorySize,
                         GEMM_SMEM_BYTES);
    cudaFuncSetAttribute(gemm_bf_t<5>, cudaFuncAttributeMaxDynamicSharedMemorySize,
                         GEMM_SMEM_BYTES);
    cudaFuncSetAttribute(gemm_qkv_bf, cudaFuncAttributeMaxDynamicSharedMemorySize,
                         GEMM_SMEM_BYTES);

    const int T = 256;
    const int MB = (NNODES + 127) / 128;   // 391
    // fused prep: qc fold + node/rel cvt + all weight cvt
    prep_kernel<<<(NN4 + T - 1) / T, T>>>(node, rel, qemb, Wq, bq, Wk, bk,
                                          Wv, Wo, W1, W2);

    // QKV projections (single-term bf16 tensor core) -> bf16 q/k/v
    gemm_qkv_bf<<<dim3(MB, 1, 3), T, GEMM_SMEM_BYTES>>>(bv, NNODES);

    // single fused edge pass: warp per edge
    int eb = (NEDGES + 7) / 8;
    edge_fused_kernel<<<eb, T>>>(ei, et);
    normalize_kernel<<<(NNODES * NHEADS + T - 1) / T, T>>>();

    // attn out + residual + LN1 fused -> xa fp32 + bf16
    gemm_bf_t<5><<<dim3(MB, 1), T, GEMM_SMEM_BYTES>>>(
        p_ah, p_woh, bo, node, p_xa, p_xh, n1g, n1b, NNODES, HDIM, HDIM);
    // FFN: W1 + GELU -> hidden bf16
    gemm_bf_t<1><<<dim3(MB, 4), T, GEMM_SMEM_BYTES>>>(
        p_xh, p_w1h, b1, nullptr, nullptr, p_hh, nullptr, nullptr,
        NNODES, HDIM, FFDIM);
    // W2 + resid(xa) + LN2 fused -> output
    gemm_bf_t<4><<<dim3(MB, 1), T, GEMM_SMEM_BYTES>>>(
        p_hh, p_w2h, b2, p_xa, out, nullptr, n2g, n2b, NNODES, FFDIM, HDIM);

    // fused relational branch
    rel_fused_kernel<<<NRELS, HDIM>>>(rel, relW, relb, Wc, bc, rng, rnb,
                                      out + (size_t)NNODES * HDIM);
}